// round 4
// baseline (speedup 1.0000x reference)
#include <cuda_runtime.h>
#include <cuda_bf16.h>

#define BB 2
#define HH 8
#define QQ 4096
#define DD 32
#define KK 1024
#define NBH 16

// Packed key fragments: [bh][Tglob(128)][s(2)][lane(32)] -> uint4 {b0hi,b1hi,b0lo,b1lo}
__device__ uint4 g_kpack[NBH * 128 * 2 * 32];

__device__ __forceinline__ unsigned pack_bf16x2(float lo_elem, float hi_elem) {
    __nv_bfloat162 r = __floats2bfloat162_rn(lo_elem, hi_elem); // .x = low half
    return *reinterpret_cast<unsigned*>(&r);
}

// ---------------- prep: rearrange keys into MMA B-fragment order ----------------
__global__ void prep_kernel(const float* __restrict__ keys) {
    int idx = blockIdx.x * 256 + threadIdx.x;        // 131072 total
    int l  = idx & 31;
    int s  = (idx >> 5) & 1;
    int Tg = (idx >> 6) & 127;
    int bh = idx >> 13;
    int g = l >> 2, t = l & 3;
    int n  = Tg * 8 + g;
    int d0 = s * 16 + t * 2;
    const float* kr = keys + ((size_t)bh * KK + n) * DD;
    float x0 = kr[d0], x1 = kr[d0 + 1], x2 = kr[d0 + 8], x3 = kr[d0 + 9];
    float h0 = __bfloat162float(__float2bfloat16(x0));
    float h1 = __bfloat162float(__float2bfloat16(x1));
    float h2 = __bfloat162float(__float2bfloat16(x2));
    float h3 = __bfloat162float(__float2bfloat16(x3));
    uint4 v;
    v.x = pack_bf16x2(h0, h1);
    v.y = pack_bf16x2(h2, h3);
    v.z = pack_bf16x2(x0 - h0, x1 - h1);
    v.w = pack_bf16x2(x2 - h2, x3 - h3);
    g_kpack[idx] = v;
}

// ---------------- main kernel ----------------
__device__ __forceinline__ void mma16816(float* c, const unsigned* a, unsigned b0, unsigned b1) {
    asm volatile(
        "mma.sync.aligned.m16n8k16.row.col.f32.bf16.bf16.f32 "
        "{%0,%1,%2,%3}, {%4,%5,%6,%7}, {%8,%9}, {%0,%1,%2,%3};"
        : "+f"(c[0]), "+f"(c[1]), "+f"(c[2]), "+f"(c[3])
        : "r"(a[0]), "r"(a[1]), "r"(a[2]), "r"(a[3]), "r"(b0), "r"(b1));
}

#define BSTRIDE 65   // odd float2 stride -> rows rotate across banks

__global__ __launch_bounds__(256, 2)
void rga_kernel(const float* __restrict__ queries,
                const int*   __restrict__ pos,
                const float* __restrict__ rel_bias,
                float*       __restrict__ out)
{
    const int bh = blockIdx.y;
    const int b  = bh >> 3;
    const int h  = bh & 7;
    const int q0 = blockIdx.x * 16;      // 16 queries per CTA (one m16 tile)
    const int tid = threadIdx.x;
    const int w  = tid >> 5;             // 0..7  n-slice (128 keys each)
    const int l  = tid & 31;
    const int g  = l >> 2, t = l & 3;
    const int n0 = w * 128;

    __shared__ float2 bias2[63 * BSTRIDE];        // pair table: (b[c], b[c+1])
    __shared__ int2   pos_sh[16];
    __shared__ __align__(16) float red[16][8];    // 16-aligned for float4 reads

    // ---- stage bias pair table for this head ----
    {
        const float* bsrc = rel_bias + (size_t)h * 63 * 63;
        for (int i = tid; i < 63 * 63; i += 256) {
            int row = i / 63;
            int c   = i - row * 63;
            float v0 = bsrc[i];
            float v1 = (c < 62) ? bsrc[i + 1] : 0.f;
            bias2[row * BSTRIDE + c] = make_float2(v0, v1);
        }
        if (tid < 16) pos_sh[tid] = ((const int2*)pos)[(size_t)b * QQ + q0 + tid];
    }

    // ---- A fragments: hi/lo bf16 split of scaled queries ----
    unsigned Ahi[2][4], Alo[2][4];
    {
        const float scale = 0.17677669529663687f;   // 1/sqrt(32)
        const float* qr0 = queries + ((size_t)bh * QQ + q0 + g) * DD;
        const float* qr1 = queries + ((size_t)bh * QQ + q0 + g + 8) * DD;
#pragma unroll
        for (int s = 0; s < 2; s++) {
            int d0 = s * 16 + 2 * t;
            float2 p0 = *(const float2*)(qr0 + d0);      // a0
            float2 p1 = *(const float2*)(qr1 + d0);      // a1
            float2 p2 = *(const float2*)(qr0 + d0 + 8);  // a2
            float2 p3 = *(const float2*)(qr1 + d0 + 8);  // a3
            float v[8] = {p0.x * scale, p0.y * scale, p1.x * scale, p1.y * scale,
                          p2.x * scale, p2.y * scale, p3.x * scale, p3.y * scale};
#pragma unroll
            for (int i = 0; i < 4; i++) {
                float h0 = __bfloat162float(__float2bfloat16(v[2 * i]));
                float h1 = __bfloat162float(__float2bfloat16(v[2 * i + 1]));
                Ahi[s][i] = pack_bf16x2(h0, h1);
                Alo[s][i] = pack_bf16x2(v[2 * i] - h0, v[2 * i + 1] - h1);
            }
        }
    }
    __syncthreads();

    // ---- MMA main loop: 16 n-tiles x 2 k-steps x 3 splits ----
    float acc[16][4];
#pragma unroll
    for (int T = 0; T < 16; T++) { acc[T][0] = acc[T][1] = acc[T][2] = acc[T][3] = 0.f; }

    const uint4* kp = g_kpack + ((size_t)bh * 128 + w * 16) * 2 * 32 + l;
#pragma unroll
    for (int T = 0; T < 16; T++) {
        uint4 k0 = kp[(2 * T)     * 32];
        uint4 k1 = kp[(2 * T + 1) * 32];
        mma16816(acc[T], Ahi[0], k0.x, k0.y);   // hi*hi  s=0
        mma16816(acc[T], Ahi[0], k0.z, k0.w);   // hi*lo
        mma16816(acc[T], Alo[0], k0.x, k0.y);   // lo*hi
        mma16816(acc[T], Ahi[1], k1.x, k1.y);   // s=1
        mma16816(acc[T], Ahi[1], k1.z, k1.w);
        mma16816(acc[T], Alo[1], k1.x, k1.y);
    }

    // ---- epilogue: bias (pair LDS.64) + exp + partial row sums ----
    int2 p0 = pos_sh[g];
    int2 p1 = pos_sh[g + 8];
    const int r0 = 31 - p0.x, c0 = 31 - p0.y;
    const int r1 = 31 - p1.x, c1 = 31 - p1.y;
    float rs0 = 0.f, rs1 = 0.f;
#pragma unroll
    for (int T = 0; T < 16; T++) {
        int i  = w * 4 + (T >> 2);          // grid row of this tile
        int jl = 8 * (T & 3) + 2 * t;       // grid col (within 32) of first element
        float2 bp0 = bias2[(i + r0) * BSTRIDE + (jl + c0)];
        float2 bp1 = bias2[(i + r1) * BSTRIDE + (jl + c1)];
        float e0 = __expf(acc[T][0] + bp0.x);
        float e1 = __expf(acc[T][1] + bp0.y);
        float e2 = __expf(acc[T][2] + bp1.x);
        float e3 = __expf(acc[T][3] + bp1.y);
        acc[T][0] = e0; acc[T][1] = e1; acc[T][2] = e2; acc[T][3] = e3;
        rs0 += e0 + e1;
        rs1 += e2 + e3;
    }
    rs0 += __shfl_xor_sync(0xFFFFFFFFu, rs0, 1);
    rs0 += __shfl_xor_sync(0xFFFFFFFFu, rs0, 2);
    rs1 += __shfl_xor_sync(0xFFFFFFFFu, rs1, 1);
    rs1 += __shfl_xor_sync(0xFFFFFFFFu, rs1, 2);
    if (t == 0) {
        red[g][w]     = rs0;
        red[g + 8][w] = rs1;
    }
    __syncthreads();

    float s0 = 0.f, s1 = 0.f;
    {
        const float4* rp0 = (const float4*)red[g];
        const float4* rp1 = (const float4*)red[g + 8];
        float4 a0 = rp0[0], a1 = rp0[1];
        float4 b0 = rp1[0], b1 = rp1[1];
        s0 = ((a0.x + a0.y) + (a0.z + a0.w)) + ((a1.x + a1.y) + (a1.z + a1.w));
        s1 = ((b0.x + b0.y) + (b0.z + b0.w)) + ((b1.x + b1.y) + (b1.z + b1.w));
    }
    float inv0 = __fdividef(1.0f, s0);
    float inv1 = __fdividef(1.0f, s1);

    float* o0 = out + ((size_t)bh * QQ + q0 + g) * KK + n0 + 2 * t;
    float* o1 = out + ((size_t)bh * QQ + q0 + g + 8) * KK + n0 + 2 * t;
#pragma unroll
    for (int T = 0; T < 16; T++) {
        *(float2*)(o0 + 8 * T) = make_float2(acc[T][0] * inv0, acc[T][1] * inv0);
        *(float2*)(o1 + 8 * T) = make_float2(acc[T][2] * inv1, acc[T][3] * inv1);
    }
}

extern "C" void kernel_launch(void* const* d_in, const int* in_sizes, int n_in,
                              void* d_out, int out_size)
{
    const float* queries  = (const float*)d_in[0];
    const float* keys     = (const float*)d_in[1];
    const int*   pos      = (const int*)  d_in[2];
    const float* rel_bias = (const float*)d_in[3];
    float*       out      = (float*)d_out;

    prep_kernel<<<512, 256>>>(keys);
    dim3 grid(QQ / 16, NBH);          // (256, 16) CTAs of 256 threads
    rga_kernel<<<grid, dim3(256)>>>(queries, pos, rel_bias, out);
}

// round 6
// speedup vs baseline: 1.0911x; 1.0911x over previous
#include <cuda_runtime.h>
#include <cuda_bf16.h>

#define BB 2
#define HH 8
#define QQ 4096
#define DD 32
#define KK 1024
#define NBH 16

// Packed key fragments: [bh][Tglob(128)][s(2)][lane(32)] -> uint4 {b0hi,b1hi,b0lo,b1lo}
__device__ uint4 g_kpack[NBH * 128 * 2 * 32];

__device__ __forceinline__ unsigned pack_bf16x2(float lo_elem, float hi_elem) {
    __nv_bfloat162 r = __floats2bfloat162_rn(lo_elem, hi_elem); // .x = low half
    return *reinterpret_cast<unsigned*>(&r);
}

__device__ __forceinline__ float ex2f(float x) {
    float r;
    asm("ex2.approx.f32 %0, %1;" : "=f"(r) : "f"(x));
    return r;
}

// ---------------- prep: rearrange keys into MMA B-fragment order ----------------
__global__ void prep_kernel(const float* __restrict__ keys) {
    int idx = blockIdx.x * 256 + threadIdx.x;        // 131072 total
    int l  = idx & 31;
    int s  = (idx >> 5) & 1;
    int Tg = (idx >> 6) & 127;
    int bh = idx >> 13;
    int g = l >> 2, t = l & 3;
    int n  = Tg * 8 + g;
    int d0 = s * 16 + t * 2;
    const float* kr = keys + ((size_t)bh * KK + n) * DD;
    float x0 = kr[d0], x1 = kr[d0 + 1], x2 = kr[d0 + 8], x3 = kr[d0 + 9];
    float h0 = __bfloat162float(__float2bfloat16(x0));
    float h1 = __bfloat162float(__float2bfloat16(x1));
    float h2 = __bfloat162float(__float2bfloat16(x2));
    float h3 = __bfloat162float(__float2bfloat16(x3));
    uint4 v;
    v.x = pack_bf16x2(h0, h1);
    v.y = pack_bf16x2(h2, h3);
    v.z = pack_bf16x2(x0 - h0, x1 - h1);
    v.w = pack_bf16x2(x2 - h2, x3 - h3);
    g_kpack[idx] = v;
}

// ---------------- main kernel ----------------
__device__ __forceinline__ void mma16816(float* c, const unsigned* a, unsigned b0, unsigned b1) {
    asm volatile(
        "mma.sync.aligned.m16n8k16.row.col.f32.bf16.bf16.f32 "
        "{%0,%1,%2,%3}, {%4,%5,%6,%7}, {%8,%9}, {%0,%1,%2,%3};"
        : "+f"(c[0]), "+f"(c[1]), "+f"(c[2]), "+f"(c[3])
        : "r"(a[0]), "r"(a[1]), "r"(a[2]), "r"(a[3]), "r"(b0), "r"(b1));
}

#define BSTRIDE 65   // odd float2 stride -> rows rotate across banks
#define LOG2E 1.4426950408889634f

__global__ __launch_bounds__(512, 1)
void rga_kernel(const float* __restrict__ queries,
                const int*   __restrict__ pos,
                const float* __restrict__ rel_bias,
                float*       __restrict__ out)
{
    const int bh = blockIdx.y;
    const int b  = bh >> 3;
    const int h  = bh & 7;
    const int q0 = blockIdx.x * 32;      // 32 queries per CTA (two m16 tiles)
    const int tid = threadIdx.x;
    const int w  = tid >> 5;
    const int l  = tid & 31;
    const int qt = w >> 3;               // 0..1 q-tile
    const int nw = w & 7;                // 0..7 n-slice (128 keys)
    const int g  = l >> 2, t = l & 3;
    const int m0 = q0 + qt * 16;
    const int n0 = nw * 128;

    __shared__ float2 bias2[63 * BSTRIDE];        // (b[c], b[c+1]) * log2e
    __shared__ int2   pos_sh[32];
    __shared__ __align__(16) float red[32][8];

    // ---- issue bias/pos staging (no barrier yet: hides behind MMA loop) ----
    {
        const float* bsrc = rel_bias + (size_t)h * 63 * 63;
        for (int i = tid; i < 63 * 63; i += 512) {
            int row = i / 63;
            int c   = i - row * 63;
            float v0 = bsrc[i] * LOG2E;
            float v1 = (c < 62) ? bsrc[i + 1] * LOG2E : 0.f;
            bias2[row * BSTRIDE + c] = make_float2(v0, v1);
        }
        if (tid < 32) pos_sh[tid] = ((const int2*)pos)[(size_t)b * QQ + q0 + tid];
    }

    // ---- A fragments: hi/lo bf16 split of (scale*log2e)-scaled queries ----
    unsigned Ahi[2][4], Alo[2][4];
    {
        const float scale = 0.17677669529663687f * LOG2E;   // 1/sqrt(32) * log2e
        const float* qr0 = queries + ((size_t)bh * QQ + m0 + g) * DD;
        const float* qr1 = queries + ((size_t)bh * QQ + m0 + g + 8) * DD;
#pragma unroll
        for (int s = 0; s < 2; s++) {
            int d0 = s * 16 + 2 * t;
            float2 p0 = *(const float2*)(qr0 + d0);
            float2 p1 = *(const float2*)(qr1 + d0);
            float2 p2 = *(const float2*)(qr0 + d0 + 8);
            float2 p3 = *(const float2*)(qr1 + d0 + 8);
            float v[8] = {p0.x * scale, p0.y * scale, p1.x * scale, p1.y * scale,
                          p2.x * scale, p2.y * scale, p3.x * scale, p3.y * scale};
#pragma unroll
            for (int i = 0; i < 4; i++) {
                float h0 = __bfloat162float(__float2bfloat16(v[2 * i]));
                float h1 = __bfloat162float(__float2bfloat16(v[2 * i + 1]));
                Ahi[s][i] = pack_bf16x2(h0, h1);
                Alo[s][i] = pack_bf16x2(v[2 * i] - h0, v[2 * i + 1] - h1);
            }
        }
    }

    // ---- MMA main loop: 16 n-tiles x 2 k-steps x 3 splits (acc in log2 units) ----
    float acc[16][4];
#pragma unroll
    for (int T = 0; T < 16; T++) { acc[T][0] = acc[T][1] = acc[T][2] = acc[T][3] = 0.f; }

    const uint4* kp = g_kpack + ((size_t)bh * 128 + nw * 16) * 2 * 32 + l;
#pragma unroll
    for (int T = 0; T < 16; T++) {
        uint4 k0 = kp[(2 * T)     * 32];
        uint4 k1 = kp[(2 * T + 1) * 32];
        mma16816(acc[T], Ahi[0], k0.x, k0.y);   // hi*hi  s=0
        mma16816(acc[T], Ahi[0], k0.z, k0.w);   // hi*lo
        mma16816(acc[T], Alo[0], k0.x, k0.y);   // lo*hi
        mma16816(acc[T], Ahi[1], k1.x, k1.y);   // s=1
        mma16816(acc[T], Ahi[1], k1.z, k1.w);
        mma16816(acc[T], Alo[1], k1.x, k1.y);
    }
    __syncthreads();   // bias table + pos now visible

    // ---- epilogue: bias (LDS.64 pair) + exp2 + partial row sums ----
    int2 p0 = pos_sh[qt * 16 + g];
    int2 p1 = pos_sh[qt * 16 + g + 8];
    const int r0 = 31 - p0.x, c0 = 31 - p0.y;
    const int r1 = 31 - p1.x, c1 = 31 - p1.y;
    float rs0 = 0.f, rs1 = 0.f;
#pragma unroll
    for (int T = 0; T < 16; T++) {
        int i  = nw * 4 + (T >> 2);         // grid row of this tile
        int jl = 8 * (T & 3) + 2 * t;       // grid col (within 32) of first element
        float2 bp0 = bias2[(i + r0) * BSTRIDE + (jl + c0)];
        float2 bp1 = bias2[(i + r1) * BSTRIDE + (jl + c1)];
        float e0 = ex2f(acc[T][0] + bp0.x);
        float e1 = ex2f(acc[T][1] + bp0.y);
        float e2 = ex2f(acc[T][2] + bp1.x);
        float e3 = ex2f(acc[T][3] + bp1.y);
        acc[T][0] = e0; acc[T][1] = e1; acc[T][2] = e2; acc[T][3] = e3;
        rs0 += e0 + e1;
        rs1 += e2 + e3;
    }
    rs0 += __shfl_xor_sync(0xFFFFFFFFu, rs0, 1);
    rs0 += __shfl_xor_sync(0xFFFFFFFFu, rs0, 2);
    rs1 += __shfl_xor_sync(0xFFFFFFFFu, rs1, 1);
    rs1 += __shfl_xor_sync(0xFFFFFFFFu, rs1, 2);
    if (t == 0) {
        red[qt * 16 + g][nw]     = rs0;
        red[qt * 16 + g + 8][nw] = rs1;
    }
    __syncthreads();

    float s0, s1;
    {
        const float4* rp0 = (const float4*)red[qt * 16 + g];
        const float4* rp1 = (const float4*)red[qt * 16 + g + 8];
        float4 a0 = rp0[0], a1 = rp0[1];
        float4 b0 = rp1[0], b1 = rp1[1];
        s0 = ((a0.x + a0.y) + (a0.z + a0.w)) + ((a1.x + a1.y) + (a1.z + a1.w));
        s1 = ((b0.x + b0.y) + (b0.z + b0.w)) + ((b1.x + b1.y) + (b1.z + b1.w));
    }
    float inv0 = __fdividef(1.0f, s0);
    float inv1 = __fdividef(1.0f, s1);

    float* o0 = out + ((size_t)bh * QQ + m0 + g) * KK + n0 + 2 * t;
    float* o1 = out + ((size_t)bh * QQ + m0 + g + 8) * KK + n0 + 2 * t;
#pragma unroll
    for (int T = 0; T < 16; T++) {
        *(float2*)(o0 + 8 * T) = make_float2(acc[T][0] * inv0, acc[T][1] * inv0);
        *(float2*)(o1 + 8 * T) = make_float2(acc[T][2] * inv1, acc[T][3] * inv1);
    }
}

extern "C" void kernel_launch(void* const* d_in, const int* in_sizes, int n_in,
                              void* d_out, int out_size)
{
    const float* queries  = (const float*)d_in[0];
    const float* keys     = (const float*)d_in[1];
    const int*   pos      = (const int*)  d_in[2];
    const float* rel_bias = (const float*)d_in[3];
    float*       out      = (float*)d_out;

    prep_kernel<<<512, 256>>>(keys);
    dim3 grid(QQ / 32, NBH);          // (128, 16) CTAs of 512 threads
    rga_kernel<<<grid, dim3(512)>>>(queries, pos, rel_bias, out);
}

// round 8
// speedup vs baseline: 1.2535x; 1.1488x over previous
#include <cuda_runtime.h>
#include <cuda_bf16.h>

#define BB 2
#define HH 8
#define QQ 4096
#define DD 32
#define KK 1024
#define NBH 16
#define LOG2E 1.4426950408889634f

// Packed key fragments: [bh][Tglob(128)][s(2)][lane(32)] -> uint4 {b0hi,b1hi,b0lo,b1lo}
// Key order PERMUTED so C-fragment thread t owns 4 consecutive keys per tile pair.
__device__ uint4 g_kpack[NBH * 128 * 2 * 32];
// Overlapping bias quads: [h][row(63)][c(64)] -> (b[c],b[c+1],b[c+2],b[c+3]) * log2e
__device__ float4 g_bias4[HH * 63 * 64];

__device__ __forceinline__ unsigned pack_bf16x2(float lo_elem, float hi_elem) {
    __nv_bfloat162 r = __floats2bfloat162_rn(lo_elem, hi_elem);
    return *reinterpret_cast<unsigned*>(&r);
}
__device__ __forceinline__ float ex2f(float x) {
    float r;
    asm("ex2.approx.f32 %0, %1;" : "=f"(r) : "f"(x));
    return r;
}

// ---------------- prep 1: keys -> MMA B-fragment order (permuted) ----------------
__global__ void prep_kernel(const float* __restrict__ keys) {
    int idx = blockIdx.x * 256 + threadIdx.x;        // 131072 total
    int l  = idx & 31;
    int s  = (idx >> 5) & 1;
    int Tg = (idx >> 6) & 127;
    int bh = idx >> 13;
    int g = l >> 2, t = l & 3;
    // permutation: tile pair (2T,2T+1), frag col g -> phys key 16T + 4*(g>>1)... see theory
    int n  = (Tg >> 1) * 16 + (g >> 1) * 4 + (Tg & 1) * 2 + (g & 1);
    int d0 = s * 16 + t * 2;
    const float* kr = keys + ((size_t)bh * KK + n) * DD;
    float x0 = kr[d0], x1 = kr[d0 + 1], x2 = kr[d0 + 8], x3 = kr[d0 + 9];
    float h0 = __bfloat162float(__float2bfloat16(x0));
    float h1 = __bfloat162float(__float2bfloat16(x1));
    float h2 = __bfloat162float(__float2bfloat16(x2));
    float h3 = __bfloat162float(__float2bfloat16(x3));
    uint4 v;
    v.x = pack_bf16x2(h0, h1);
    v.y = pack_bf16x2(h2, h3);
    v.z = pack_bf16x2(x0 - h0, x1 - h1);
    v.w = pack_bf16x2(x2 - h2, x3 - h3);
    g_kpack[idx] = v;
}

// ---------------- prep 2: bias -> overlapping quad table (x log2e) ----------------
__global__ void prep_bias(const float* __restrict__ rel_bias) {
    int idx = blockIdx.x * 256 + threadIdx.x;        // HH*63*64 = 32256 total
    if (idx >= HH * 63 * 64) return;
    int c   = idx & 63;
    int row = (idx >> 6) % 63;
    int h   = idx / (63 * 64);
    const float* src = rel_bias + ((size_t)h * 63 + row) * 63;
    float4 v;
    v.x = (c + 0 < 63) ? src[c + 0] * LOG2E : 0.f;
    v.y = (c + 1 < 63) ? src[c + 1] * LOG2E : 0.f;
    v.z = (c + 2 < 63) ? src[c + 2] * LOG2E : 0.f;
    v.w = (c + 3 < 63) ? src[c + 3] * LOG2E : 0.f;
    g_bias4[idx] = v;
}

// ---------------- main kernel ----------------
__device__ __forceinline__ void mma16816(float* c, const unsigned* a, unsigned b0, unsigned b1) {
    asm volatile(
        "mma.sync.aligned.m16n8k16.row.col.f32.bf16.bf16.f32 "
        "{%0,%1,%2,%3}, {%4,%5,%6,%7}, {%8,%9}, {%0,%1,%2,%3};"
        : "+f"(c[0]), "+f"(c[1]), "+f"(c[2]), "+f"(c[3])
        : "r"(a[0]), "r"(a[1]), "r"(a[2]), "r"(a[3]), "r"(b0), "r"(b1));
}

__global__ __launch_bounds__(256, 2)
void rga_kernel(const float* __restrict__ queries,
                const int*   __restrict__ pos,
                float*       __restrict__ out)
{
    const int bh = blockIdx.y;
    const int b  = bh >> 3;
    const int h  = bh & 7;
    const int q0 = blockIdx.x * 16;      // 16 queries per CTA (one m16 tile)
    const int tid = threadIdx.x;
    const int w  = tid >> 5;             // 0..7 n-slice (128 keys)
    const int l  = tid & 31;
    const int g  = l >> 2, t = l & 3;
    const int n0 = w * 128;

    __shared__ __align__(16) float red[16][8];

    // ---- pos + bias base pointers (issued early; latency hides behind A-frag/MMA) ----
    int2 p0 = ((const int2*)pos)[(size_t)b * QQ + q0 + g];
    int2 p1 = ((const int2*)pos)[(size_t)b * QQ + q0 + g + 8];
    const float4* bq0 = g_bias4 + (size_t)h * 63 * 64 + (31 - p0.x) * 64 + (31 - p0.y);
    const float4* bq1 = g_bias4 + (size_t)h * 63 * 64 + (31 - p1.x) * 64 + (31 - p1.y);

    // ---- A fragments: hi/lo bf16 split of (scale*log2e)-scaled queries ----
    unsigned Ahi[2][4], Alo[2][4];
    {
        const float scale = 0.17677669529663687f * LOG2E;
        const float* qr0 = queries + ((size_t)bh * QQ + q0 + g) * DD;
        const float* qr1 = queries + ((size_t)bh * QQ + q0 + g + 8) * DD;
#pragma unroll
        for (int s = 0; s < 2; s++) {
            int d0 = s * 16 + 2 * t;
            float2 f0 = *(const float2*)(qr0 + d0);
            float2 f1 = *(const float2*)(qr1 + d0);
            float2 f2 = *(const float2*)(qr0 + d0 + 8);
            float2 f3 = *(const float2*)(qr1 + d0 + 8);
            float v[8] = {f0.x * scale, f0.y * scale, f1.x * scale, f1.y * scale,
                          f2.x * scale, f2.y * scale, f3.x * scale, f3.y * scale};
#pragma unroll
            for (int i = 0; i < 4; i++) {
                float h0 = __bfloat162float(__float2bfloat16(v[2 * i]));
                float h1 = __bfloat162float(__float2bfloat16(v[2 * i + 1]));
                Ahi[s][i] = pack_bf16x2(h0, h1);
                Alo[s][i] = pack_bf16x2(v[2 * i] - h0, v[2 * i + 1] - h1);
            }
        }
    }

    // ---- MMA main loop: 16 n-tiles x 2 k-steps x 3 splits ----
    float acc[16][4];
#pragma unroll
    for (int T = 0; T < 16; T++) { acc[T][0] = acc[T][1] = acc[T][2] = acc[T][3] = 0.f; }

    const uint4* kp = g_kpack + ((size_t)bh * 128 + w * 16) * 2 * 32 + l;
#pragma unroll
    for (int T = 0; T < 16; T++) {
        uint4 k0 = kp[(2 * T)     * 32];
        uint4 k1 = kp[(2 * T + 1) * 32];
        mma16816(acc[T], Ahi[0], k0.x, k0.y);   // hi*hi  s=0
        mma16816(acc[T], Ahi[0], k0.z, k0.w);   // hi*lo
        mma16816(acc[T], Alo[0], k0.x, k0.y);   // lo*hi
        mma16816(acc[T], Ahi[1], k1.x, k1.y);   // s=1
        mma16816(acc[T], Ahi[1], k1.z, k1.w);
        mma16816(acc[T], Alo[1], k1.x, k1.y);
    }

    // ---- epilogue: per tile-pair P, thread owns 4 consecutive keys / q-row ----
    float rs0 = 0.f, rs1 = 0.f;
#pragma unroll
    for (int P = 0; P < 8; P++) {
        int off = (w * 4 + (P >> 1)) * 64 + (P & 1) * 16 + 4 * t;   // row*64 + col
        float4 b0 = bq0[off];
        float4 b1 = bq1[off];
        float e0 = ex2f(acc[2 * P][0]     + b0.x);
        float e1 = ex2f(acc[2 * P][1]     + b0.y);
        float e2 = ex2f(acc[2 * P + 1][0] + b0.z);
        float e3 = ex2f(acc[2 * P + 1][1] + b0.w);
        float f0 = ex2f(acc[2 * P][2]     + b1.x);
        float f1 = ex2f(acc[2 * P][3]     + b1.y);
        float f2 = ex2f(acc[2 * P + 1][2] + b1.z);
        float f3 = ex2f(acc[2 * P + 1][3] + b1.w);
        acc[2 * P][0] = e0; acc[2 * P][1] = e1; acc[2 * P + 1][0] = e2; acc[2 * P + 1][1] = e3;
        acc[2 * P][2] = f0; acc[2 * P][3] = f1; acc[2 * P + 1][2] = f2; acc[2 * P + 1][3] = f3;
        rs0 += (e0 + e1) + (e2 + e3);
        rs1 += (f0 + f1) + (f2 + f3);
    }
    rs0 += __shfl_xor_sync(0xFFFFFFFFu, rs0, 1);
    rs0 += __shfl_xor_sync(0xFFFFFFFFu, rs0, 2);
    rs1 += __shfl_xor_sync(0xFFFFFFFFu, rs1, 1);
    rs1 += __shfl_xor_sync(0xFFFFFFFFu, rs1, 2);
    if (t == 0) {
        red[g][w]     = rs0;
        red[g + 8][w] = rs1;
    }
    __syncthreads();

    float s0, s1;
    {
        const float4* rp0 = (const float4*)red[g];
        const float4* rp1 = (const float4*)red[g + 8];
        float4 a0 = rp0[0], a1 = rp0[1];
        float4 c0 = rp1[0], c1 = rp1[1];
        s0 = ((a0.x + a0.y) + (a0.z + a0.w)) + ((a1.x + a1.y) + (a1.z + a1.w));
        s1 = ((c0.x + c0.y) + (c0.z + c0.w)) + ((c1.x + c1.y) + (c1.z + c1.w));
    }
    float inv0 = __fdividef(1.0f, s0);
    float inv1 = __fdividef(1.0f, s1);

    // ---- stores: 4 consecutive keys per thread per tile-pair -> STG.128 ----
    float* o0 = out + ((size_t)bh * QQ + q0 + g) * KK + n0 + 4 * t;
    float* o1 = out + ((size_t)bh * QQ + q0 + g + 8) * KK + n0 + 4 * t;
#pragma unroll
    for (int P = 0; P < 8; P++) {
        *(float4*)(o0 + 16 * P) = make_float4(acc[2 * P][0] * inv0, acc[2 * P][1] * inv0,
                                              acc[2 * P + 1][0] * inv0, acc[2 * P + 1][1] * inv0);
        *(float4*)(o1 + 16 * P) = make_float4(acc[2 * P][2] * inv1, acc[2 * P][3] * inv1,
                                              acc[2 * P + 1][2] * inv1, acc[2 * P + 1][3] * inv1);
    }
}

extern "C" void kernel_launch(void* const* d_in, const int* in_sizes, int n_in,
                              void* d_out, int out_size)
{
    const float* queries  = (const float*)d_in[0];
    const float* keys     = (const float*)d_in[1];
    const int*   pos      = (const int*)  d_in[2];
    const float* rel_bias = (const float*)d_in[3];
    float*       out      = (float*)d_out;

    prep_kernel<<<512, 256>>>(keys);
    prep_bias<<<(HH * 63 * 64 + 255) / 256, 256>>>(rel_bias);
    dim3 grid(QQ / 16, NBH);          // (256, 16) CTAs of 256 threads
    rga_kernel<<<grid, dim3(256)>>>(queries, pos, out);
}